// round 17
// baseline (speedup 1.0000x reference)
#include <cuda_runtime.h>
#include <cuda_fp16.h>
#include <math.h>
#include <stdint.h>

#define NBATCH 2
#define TSEQ   2048
#define EMB    1024
#define NHEAD  16
#define HDIM   64
#define NTOK   (NBATCH*TSEQ)   // 4096

// ---------------------------------------------------------------------------
// Persistent hi/lo half scratch (allocation-free)
// ---------------------------------------------------------------------------
__device__ __half g_xh[NTOK*EMB],  g_xl[NTOK*EMB];                 // x split
__device__ __half g_wh[3*NHEAD*EMB*HDIM], g_wl[3*NHEAD*EMB*HDIM]; // Wq|Wk|Wv split
__device__ __half g_woh[EMB*EMB], g_wol[EMB*EMB];                 // Wo split
__device__ __half g_qh[NBATCH*NHEAD*TSEQ*HDIM], g_ql[NBATCH*NHEAD*TSEQ*HDIM];
__device__ __half g_kh[NBATCH*NHEAD*TSEQ*HDIM], g_kl[NBATCH*NHEAD*TSEQ*HDIM];
__device__ __half g_vh[NBATCH*NHEAD*TSEQ*HDIM];
__device__ __half g_ch[NTOK*EMB];                                  // attn combined (f16 only)

// ===========================================================================
// Helpers
// ===========================================================================
__device__ __forceinline__ uint32_t smem_u32(const void* p) {
    uint32_t a;
    asm("{ .reg .u64 t; cvta.to.shared.u64 t, %1; cvt.u32.u64 %0, t; }" : "=r"(a) : "l"(p));
    return a;
}
#define CP_ASYNC16(dst, src) asm volatile("cp.async.cg.shared.global [%0], [%1], 16;" :: "r"(dst), "l"(src))
#define CP_COMMIT()          asm volatile("cp.async.commit_group;" ::: "memory")
#define CP_WAIT0()           asm volatile("cp.async.wait_group 0;" ::: "memory")
#define CP_WAIT1()           asm volatile("cp.async.wait_group 1;" ::: "memory")
#define CP_WAIT2()           asm volatile("cp.async.wait_group 2;" ::: "memory")

__device__ __forceinline__ void mma_f16(float* d, const uint32_t* a, const uint32_t* b) {
    asm volatile("mma.sync.aligned.m16n8k16.row.col.f32.f16.f16.f32 "
        "{%0,%1,%2,%3}, {%4,%5,%6,%7}, {%8,%9}, {%0,%1,%2,%3};"
        : "+f"(d[0]), "+f"(d[1]), "+f"(d[2]), "+f"(d[3])
        : "r"(a[0]), "r"(a[1]), "r"(a[2]), "r"(a[3]), "r"(b[0]), "r"(b[1]));
}
__device__ __forceinline__ void ldsm4(uint32_t* r, uint32_t a) {
    asm volatile("ldmatrix.sync.aligned.m8n8.x4.shared.b16 {%0,%1,%2,%3}, [%4];"
        : "=r"(r[0]), "=r"(r[1]), "=r"(r[2]), "=r"(r[3]) : "r"(a));
}
__device__ __forceinline__ void ldsm4t(uint32_t* r, uint32_t a) {
    asm volatile("ldmatrix.sync.aligned.m8n8.x4.trans.shared.b16 {%0,%1,%2,%3}, [%4];"
        : "=r"(r[0]), "=r"(r[1]), "=r"(r[2]), "=r"(r[3]) : "r"(a));
}
__device__ __forceinline__ uint32_t pack_h2(float a, float b) {
    __half2 h = __floats2half2_rn(a, b);
    return *(uint32_t*)&h;
}
__device__ __forceinline__ void split_wr2(float a, float b, __half* ph, __half* pl) {
    __half ha = __float2half_rn(a), hb = __float2half_rn(b);
    __half la = __float2half_rn(a - __half2float(ha));
    __half lb = __float2half_rn(b - __half2float(hb));
    *(uint32_t*)ph = ((uint32_t)__half_as_ushort(hb) << 16) | (uint32_t)__half_as_ushort(ha);
    *(uint32_t*)pl = ((uint32_t)__half_as_ushort(lb) << 16) | (uint32_t)__half_as_ushort(la);
}
// exp2 on fma pipe (no MUFU); valid for y <= 0
__device__ __forceinline__ float exp2p(float y) {
    y = fmaxf(y, -126.f);
    float r = rintf(y);
    float f = y - r;
    float p = fmaf(f, 1.3333558146e-3f, 9.6181291076e-3f);
    p = fmaf(f, p, 5.5504108664e-2f);
    p = fmaf(f, p, 2.4022650696e-1f);
    p = fmaf(f, p, 6.9314718056e-1f);
    p = fmaf(f, p, 1.0f);
    int n = (int)r;
    return p * __int_as_float((n + 127) << 23);
}

#define QSC 0.18033688011112042f  // 0.125 * log2(e)

// ---------------------------------------------------------------------------
// Kernel 0: prep — split x, Wq/Wk/Wv, Wo into hi/lo halves
// ---------------------------------------------------------------------------
#define PREP_NX2  (NTOK*EMB/2)
#define PREP_NW2  (NHEAD*EMB*HDIM/2)
#define PREP_NWO2 (EMB*EMB/2)
#define PREP_TOT  (PREP_NX2 + 3*PREP_NW2 + PREP_NWO2)

__device__ __forceinline__ void split2_store(const float* s, __half* h, __half* l, int i2) {
    float2 v = ((const float2*)s)[i2];
    __half2 hv = __floats2half2_rn(v.x, v.y);
    float2 hr = __half22float2(hv);
    __half2 lv = __floats2half2_rn(v.x - hr.x, v.y - hr.y);
    ((__half2*)h)[i2] = hv;
    ((__half2*)l)[i2] = lv;
}

__global__ __launch_bounds__(256) void prep_kernel(
    const float* __restrict__ x, const float* __restrict__ Wq,
    const float* __restrict__ Wk, const float* __restrict__ Wv,
    const float* __restrict__ Wo)
{
    int idx = blockIdx.x * 256 + threadIdx.x;
    if (idx < PREP_NX2) { split2_store(x, g_xh, g_xl, idx); return; }
    idx -= PREP_NX2;
    if (idx < PREP_NW2) { split2_store(Wq, g_wh, g_wl, idx); return; }
    idx -= PREP_NW2;
    if (idx < PREP_NW2) { split2_store(Wk, g_wh + NHEAD*EMB*HDIM, g_wl + NHEAD*EMB*HDIM, idx); return; }
    idx -= PREP_NW2;
    if (idx < PREP_NW2) { split2_store(Wv, g_wh + 2*NHEAD*EMB*HDIM, g_wl + 2*NHEAD*EMB*HDIM, idx); return; }
    idx -= PREP_NW2;
    if (idx < PREP_NWO2) split2_store(Wo, g_woh, g_wol, idx);
}

// ---------------------------------------------------------------------------
// Kernel 1: FUSED QKV projection [4096 x 1024] @ [1024 x 3072].
// grid=(32,24), 256 thr, block 128x128, warp 64x32. 3-stage ring, 1 sync/chunk.
// ---------------------------------------------------------------------------
#define FQ_KC   32
#define FQ_NCH  (EMB / FQ_KC)    // 32
#define BA_AL   10240            // byte offsets within buffer
#define BA_BH   20480
#define BA_BL   29184
#define FQ_BUFB 37888
#define QKV_SMEM (3 * FQ_BUFB)   // 113664 B

__device__ __forceinline__ void fqkv_stage(uint32_t sbuf,
    const __half* wbh, const __half* wbl,
    int m0, int k0, int tid, bool need_alo)
{
    #pragma unroll
    for (int j = 0; j < 2; j++) {           // A hi: 512 cp (128 rows x 4)
        int idx = j * 256 + tid;
        int r = idx >> 2, q = idx & 3;
        CP_ASYNC16(sbuf + (uint32_t)(r*40 + q*8)*2,
                   g_xh + (size_t)(m0 + r)*EMB + k0 + q*8);
    }
    if (need_alo) {
        #pragma unroll
        for (int j = 0; j < 2; j++) {       // A lo
            int idx = j * 256 + tid;
            int r = idx >> 2, q = idx & 3;
            CP_ASYNC16(sbuf + BA_AL + (uint32_t)(r*40 + q*8)*2,
                       g_xl + (size_t)(m0 + r)*EMB + k0 + q*8);
        }
    }
    #pragma unroll
    for (int j = 0; j < 2; j++) {           // B: 32 k-rows x 128 n
        int idx = j * 256 + tid;
        int k = idx >> 4, c = (idx & 15) * 8;
        size_t src = (size_t)(c >> 6) * (EMB*HDIM) + (size_t)(k0 + k)*HDIM + (c & 63);
        CP_ASYNC16(sbuf + BA_BH + (uint32_t)(k*136 + c)*2, wbh + src);
        CP_ASYNC16(sbuf + BA_BL + (uint32_t)(k*136 + c)*2, wbl + src);
    }
    CP_COMMIT();
}

__global__ __launch_bounds__(256, 2) void qkv_mma_kernel()
{
    extern __shared__ __align__(16) char sm[];
    const uint32_t sb = smem_u32(sm);
    const int tid = threadIdx.x;
    const int lane = tid & 31, wid = tid >> 5;
    const int gid = lane >> 2, tig = lane & 3;
    const int warp_m = wid >> 2;       // 0..1 (64 rows)
    const int warp_n = wid & 3;        // 0..3 (32 cols)
    const int m0 = blockIdx.x * 128;
    const int n0 = blockIdx.y * 128;
    const int which = n0 >> 10;
    const bool three_pass = (which != 2);

    const __half* wbh = g_wh + (size_t)(n0 >> 6) * (EMB*HDIM);
    const __half* wbl = g_wl + (size_t)(n0 >> 6) * (EMB*HDIM);

    const int offA  = ((lane & 7) + ((lane >> 3) & 1) * 8) * 40  + (lane >> 4) * 8;
    const int offBt = ((lane & 7) + ((lane >> 3) & 1) * 8) * 136 + (lane >> 4) * 8;

    float acc[4][4][4];
    #pragma unroll
    for (int mt = 0; mt < 4; mt++)
        #pragma unroll
        for (int nt = 0; nt < 4; nt++)
            #pragma unroll
            for (int e = 0; e < 4; e++) acc[mt][nt][e] = 0.f;

    fqkv_stage(sb, wbh, wbl, m0, 0, tid, three_pass);
    fqkv_stage(sb + FQ_BUFB, wbh, wbl, m0, FQ_KC, tid, three_pass);

    for (int ch = 0; ch < FQ_NCH; ch++) {
        if (ch + 1 < FQ_NCH) CP_WAIT1(); else CP_WAIT0();
        __syncthreads();
        if (ch + 2 < FQ_NCH)
            fqkv_stage(sb + ((ch + 2) % 3) * FQ_BUFB, wbh, wbl, m0, (ch + 2) * FQ_KC, tid, three_pass);

        const uint32_t bb = sb + (ch % 3) * FQ_BUFB;
        #pragma unroll
        for (int ks = 0; ks < 2; ks++) {
            uint32_t ahf[4][4], alf[4][4];
            #pragma unroll
            for (int mt = 0; mt < 4; mt++) {
                uint32_t ao = (uint32_t)(offA + (warp_m*64 + mt*16)*40 + ks*16) * 2;
                ldsm4(ahf[mt], bb + ao);
                if (three_pass) ldsm4(alf[mt], bb + BA_AL + ao);
            }
            #pragma unroll
            for (int ntp = 0; ntp < 2; ntp++) {
                uint32_t bhf[4], blf[4];
                uint32_t bo = (uint32_t)(offBt + (ks*16)*136 + warp_n*32 + ntp*16) * 2;
                ldsm4t(bhf, bb + BA_BH + bo);
                ldsm4t(blf, bb + BA_BL + bo);
                #pragma unroll
                for (int mt = 0; mt < 4; mt++) {
                    mma_f16(acc[mt][ntp*2],   ahf[mt], bhf);
                    mma_f16(acc[mt][ntp*2],   ahf[mt], blf);
                    if (three_pass) mma_f16(acc[mt][ntp*2], alf[mt], bhf);
                    mma_f16(acc[mt][ntp*2+1], ahf[mt], bhf + 2);
                    mma_f16(acc[mt][ntp*2+1], ahf[mt], blf + 2);
                    if (three_pass) mma_f16(acc[mt][ntp*2+1], alf[mt], bhf + 2);
                }
            }
        }
    }

    // epilogue: decode (which, h, d) from global column; Q scaled by QSC
    const float scale = (which == 0) ? QSC : 1.0f;
    #pragma unroll
    for (int mt = 0; mt < 4; mt++)
        #pragma unroll
        for (int nt = 0; nt < 4; nt++) {
            int ng = n0 + warp_n * 32 + nt * 8 + 2 * tig;
            int hh = (ng >> 6) & 15, d = ng & 63;
            #pragma unroll
            for (int half = 0; half < 2; half++) {
                int m = m0 + warp_m * 64 + mt * 16 + gid + half * 8;
                int b = m >> 11, t = m & (TSEQ - 1);
                size_t o0 = ((size_t)((b * NHEAD + hh) * TSEQ + t)) * HDIM + d;
                float v0 = acc[mt][nt][half*2]   * scale;
                float v1 = acc[mt][nt][half*2+1] * scale;
                if (which == 0)      split_wr2(v0, v1, g_qh + o0, g_ql + o0);
                else if (which == 1) split_wr2(v0, v1, g_kh + o0, g_kl + o0);
                else                 *(uint32_t*)(g_vh + o0) = pack_h2(v0, v1);
            }
        }
}

// ---------------------------------------------------------------------------
// Kernel 2: flash attention. grid=(16,16,2), 256 thr (8 warps x 16 rows).
// QK^T 3-pass; PV 1-pass. 4-stage KV ring (3 tiles in flight), 2 CTAs/SM.
// Buffer (bytes): Kh@0 Kl@9216 Vh@18432; BUFB=27648; 4 buffers = 110592.
// Q staged transiently in buffer region, extracted to regs pre-loop.
// ---------------------------------------------------------------------------
#define AS 72
#define AT_BUFB 27648
#define ATTN_SMEM (4 * AT_BUFB)   // 110592

__device__ __forceinline__ void attn_stage_kv(uint32_t sb,
    const __half* Kh, const __half* Kl, const __half* Vh,
    int kt, int tid)
{
    uint32_t bbuf = sb + (uint32_t)(kt & 3) * AT_BUFB;
    #pragma unroll
    for (int j = 0; j < 2; j++) {
        int idx = j * 256 + tid;           // 512 per array (64 rows x 8)
        int r = idx >> 3, q = idx & 7;
        uint32_t d = (uint32_t)(r * AS + q * 8) * 2;
        size_t s = (size_t)(kt * 64 + r) * HDIM + q * 8;
        CP_ASYNC16(bbuf + d,         Kh + s);
        CP_ASYNC16(bbuf + 9216 + d,  Kl + s);
        CP_ASYNC16(bbuf + 18432 + d, Vh + s);
    }
    CP_COMMIT();
}

__global__ __launch_bounds__(256, 2) void attn_mma_kernel()
{
    extern __shared__ __align__(16) char sm[];
    const uint32_t sb = smem_u32(sm);
    const int tid = threadIdx.x;
    const int lane = tid & 31, wid = tid >> 5;
    const int gid = lane >> 2, tig = lane & 3;
    const int qt = blockIdx.x, h = blockIdx.y, b = blockIdx.z;
    const size_t base = (size_t)((b * NHEAD + h) * TSEQ) * HDIM;
    const __half* Qh = g_qh + base; const __half* Ql = g_ql + base;
    const __half* Kh = g_kh + base; const __half* Kl = g_kl + base;
    const __half* Vh = g_vh + base;

    const int offQ = ((lane & 7) + ((lane >> 3) & 1) * 8) * AS + (lane >> 4) * 8; // A & trans-B
    const int offK = ((lane & 7) + (lane >> 4) * 8) * AS + ((lane >> 3) & 1) * 8; // non-trans B

    // prologue: stage Q halves into buffer region (Qh@0, Ql@18432), extract, recycle
    #pragma unroll
    for (int j = 0; j < 4; j++) {
        int idx = j * 256 + tid;           // 1024 per array (128 rows x 8)
        int r = idx >> 3, q = idx & 7;
        uint32_t d = (uint32_t)(r * AS + q * 8) * 2;
        size_t s = (size_t)(qt * 128 + r) * HDIM + q * 8;
        CP_ASYNC16(sb + d,         Qh + s);
        CP_ASYNC16(sb + 18432 + d, Ql + s);
    }
    CP_COMMIT();
    CP_WAIT0();
    __syncthreads();

    uint32_t qf_h[4][4], qf_l[4][4];
    #pragma unroll
    for (int ks = 0; ks < 4; ks++) {
        uint32_t ao = (uint32_t)(offQ + (wid * 16) * AS + ks * 16) * 2;
        ldsm4(qf_h[ks], sb + ao);
        ldsm4(qf_l[ks], sb + 18432 + ao);
    }
    __syncthreads();   // all warps done reading Q region; buffers reusable

    attn_stage_kv(sb, Kh, Kl, Vh, 0, tid);
    attn_stage_kv(sb, Kh, Kl, Vh, 1, tid);
    attn_stage_kv(sb, Kh, Kl, Vh, 2, tid);

    float o[8][4];
    #pragma unroll
    for (int nt = 0; nt < 8; nt++)
        #pragma unroll
        for (int e = 0; e < 4; e++) o[nt][e] = 0.f;
    float mr0 = -1e30f, mr1 = -1e30f, l0 = 0.f, l1 = 0.f;

    const int NT = TSEQ / 64;   // 32
    for (int kt = 0; kt < NT; kt++) {
        if (kt + 3 <= NT) CP_WAIT2();
        else if (kt + 2 <= NT) CP_WAIT1();
        else CP_WAIT0();
        __syncthreads();
        if (kt + 3 < NT) attn_stage_kv(sb, Kh, Kl, Vh, kt + 3, tid);

        const uint32_t kb = sb + (uint32_t)(kt & 3) * AT_BUFB;

        // S = Q K^T (3-pass f16), log2 units
        float s[8][4];
        #pragma unroll
        for (int nt = 0; nt < 8; nt++)
            #pragma unroll
            for (int e = 0; e < 4; e++) s[nt][e] = 0.f;

        #pragma unroll
        for (int ks = 0; ks < 4; ks++) {
            #pragma unroll
            for (int ntp = 0; ntp < 4; ntp++) {
                uint32_t bh[4], bl[4];
                uint32_t ao = (uint32_t)(offK + (ntp * 16) * AS + ks * 16) * 2;
                ldsm4(bh, kb + ao);
                ldsm4(bl, kb + 9216 + ao);
                mma_f16(s[ntp*2],   qf_h[ks], bh);
                mma_f16(s[ntp*2],   qf_h[ks], bl);
                mma_f16(s[ntp*2],   qf_l[ks], bh);
                mma_f16(s[ntp*2+1], qf_h[ks], bh + 2);
                mma_f16(s[ntp*2+1], qf_h[ks], bl + 2);
                mma_f16(s[ntp*2+1], qf_l[ks], bh + 2);
            }
        }

        // online softmax (rows gid, gid+8)
        float tm0 = -1e30f, tm1 = -1e30f;
        #pragma unroll
        for (int nt = 0; nt < 8; nt++) {
            tm0 = fmaxf(tm0, fmaxf(s[nt][0], s[nt][1]));
            tm1 = fmaxf(tm1, fmaxf(s[nt][2], s[nt][3]));
        }
        tm0 = fmaxf(tm0, __shfl_xor_sync(0xffffffffu, tm0, 1));
        tm0 = fmaxf(tm0, __shfl_xor_sync(0xffffffffu, tm0, 2));
        tm1 = fmaxf(tm1, __shfl_xor_sync(0xffffffffu, tm1, 1));
        tm1 = fmaxf(tm1, __shfl_xor_sync(0xffffffffu, tm1, 2));
        float mn0 = fmaxf(mr0, tm0), mn1 = fmaxf(mr1, tm1);
        float al0 = exp2p(mr0 - mn0), al1 = exp2p(mr1 - mn1);
        mr0 = mn0; mr1 = mn1;

        float rs0 = 0.f, rs1 = 0.f;
        #pragma unroll
        for (int nt = 0; nt < 8; nt++) {
            s[nt][0] = exp2p(s[nt][0] - mn0);
            s[nt][1] = exp2p(s[nt][1] - mn0);
            s[nt][2] = exp2p(s[nt][2] - mn1);
            s[nt][3] = exp2p(s[nt][3] - mn1);
            rs0 += s[nt][0] + s[nt][1];
            rs1 += s[nt][2] + s[nt][3];
        }
        rs0 += __shfl_xor_sync(0xffffffffu, rs0, 1);
        rs0 += __shfl_xor_sync(0xffffffffu, rs0, 2);
        rs1 += __shfl_xor_sync(0xffffffffu, rs1, 1);
        rs1 += __shfl_xor_sync(0xffffffffu, rs1, 2);
        l0 = l0 * al0 + rs0;
        l1 = l1 * al1 + rs1;
        #pragma unroll
        for (int nt = 0; nt < 8; nt++) {
            o[nt][0] *= al0; o[nt][1] *= al0;
            o[nt][2] *= al1; o[nt][3] *= al1;
        }

        // O += P V (1-pass: P_hi x V_hi); P packed in registers
        #pragma unroll
        for (int ks = 0; ks < 4; ks++) {
            uint32_t ah[4];
            ah[0] = pack_h2(s[2*ks][0],   s[2*ks][1]);
            ah[1] = pack_h2(s[2*ks][2],   s[2*ks][3]);
            ah[2] = pack_h2(s[2*ks+1][0], s[2*ks+1][1]);
            ah[3] = pack_h2(s[2*ks+1][2], s[2*ks+1][3]);
            #pragma unroll
            for (int dtp = 0; dtp < 4; dtp++) {
                uint32_t bh[4];
                uint32_t ao = (uint32_t)(offQ + (ks * 16) * AS + dtp * 16) * 2;
                ldsm4t(bh, kb + 18432 + ao);
                mma_f16(o[dtp*2],   ah, bh);
                mma_f16(o[dtp*2+1], ah, bh + 2);
            }
        }
    }

    // epilogue: normalize, write combined C as f16 (hi only)
    float inv0 = 1.f / l0, inv1 = 1.f / l1;
    int t0 = qt * 128 + wid * 16 + gid;
    #pragma unroll
    for (int nt = 0; nt < 8; nt++) {
        int col = h * HDIM + nt * 8 + 2 * tig;
        size_t o0 = (size_t)(b * TSEQ + t0) * EMB + col;
        size_t o1 = (size_t)(b * TSEQ + t0 + 8) * EMB + col;
        *(uint32_t*)(g_ch + o0) = pack_h2(o[nt][0] * inv0, o[nt][1] * inv0);
        *(uint32_t*)(g_ch + o1) = pack_h2(o[nt][2] * inv1, o[nt][3] * inv1);
    }
}

// ---------------------------------------------------------------------------
// Kernel 3: out = x + C @ Wo^T. grid=(32,8), 256 thr, block 128x128.
// Warp 64x32. 2-pass. 3-stage ring, KC=32, 1 sync/chunk, 2 CTAs/SM.
// Buffer (bytes): A(Ch)@0 (128x40x2=10240), Bh@10240, Bl@20480; BUFB=30720.
// ---------------------------------------------------------------------------
#define OP_KC   32
#define OP_NCH  (EMB / OP_KC)    // 32
#define OP_BH   10240
#define OP_BL   20480
#define OP_BUFB 30720
#define OP_SMEM (3 * OP_BUFB)    // 92160

__device__ __forceinline__ void op_stage(uint32_t sbuf, int m0, int n0, int k0, int tid) {
    #pragma unroll
    for (int j = 0; j < 2; j++) {           // A: 512 cp (128 rows x 4)
        int idx = j * 256 + tid;
        int r = idx >> 2, q = idx & 3;
        CP_ASYNC16(sbuf + (uint32_t)(r*40 + q*8)*2,
                   g_ch + (size_t)(m0 + r)*EMB + k0 + q*8);
    }
    #pragma unroll
    for (int j = 0; j < 2; j++) {           // B hi: 512 cp (128 n-rows x 4)
        int idx = j * 256 + tid;
        int r = idx >> 2, q = idx & 3;
        CP_ASYNC16(sbuf + OP_BH + (uint32_t)(r*40 + q*8)*2,
                   g_woh + (size_t)(n0 + r)*EMB + k0 + q*8);
    }
    #pragma unroll
    for (int j = 0; j < 2; j++) {           // B lo
        int idx = j * 256 + tid;
        int r = idx >> 2, q = idx & 3;
        CP_ASYNC16(sbuf + OP_BL + (uint32_t)(r*40 + q*8)*2,
                   g_wol + (size_t)(n0 + r)*EMB + k0 + q*8);
    }
    CP_COMMIT();
}

__global__ __launch_bounds__(256, 2) void outproj_mma_kernel(
    const float* __restrict__ x, float* __restrict__ out)
{
    extern __shared__ __align__(16) char sm[];
    const uint32_t sb = smem_u32(sm);
    const int tid = threadIdx.x;
    const int lane = tid & 31, wid = tid >> 5;
    const int gid = lane >> 2, tig = lane & 3;
    const int warp_m = wid >> 2;
    const int warp_n = wid & 3;
    const int m0 = blockIdx.x * 128, n0 = blockIdx.y * 128;

    const int offA = ((lane & 7) + ((lane >> 3) & 1) * 8) * 40 + (lane >> 4) * 8;
    const int offB = ((lane & 7) + (lane >> 4) * 8) * 40 + ((lane >> 3) & 1) * 8;

    float acc[4][4][4];
    #pragma unroll
    for (int mt = 0; mt < 4; mt++)
        #pragma unroll
        for (int nt = 0; nt < 4; nt++)
            #pragma unroll
            for (int e = 0; e < 4; e++) acc[mt][nt][e] = 0.f;

    op_stage(sb, m0, n0, 0, tid);
    op_stage(sb + OP_BUFB, m0, n0, OP_KC, tid);

    for (int ch = 0; ch < OP_NCH; ch++) {
        if (ch + 1 < OP_NCH) CP_WAIT1(); else CP_WAIT0();
        __syncthreads();
        if (ch + 2 < OP_NCH)
            op_stage(sb + ((ch + 2) % 3) * OP_BUFB, m0, n0, (ch + 2) * OP_KC, tid);

        const uint32_t bb = sb + (ch % 3) * OP_BUFB;
        #pragma unroll
        for (int ks = 0; ks < 2; ks++) {
            uint32_t af[4][4];
            #pragma unroll
            for (int mt = 0; mt < 4; mt++) {
                uint32_t ao = (uint32_t)(offA + (warp_m*64 + mt*16)*40 + ks*16) * 2;
                ldsm4(af[mt], bb + ao);
            }
            #pragma unroll
            for (int ntp = 0; ntp < 2; ntp++) {
                uint32_t bhf[4], blf[4];
                uint32_t bo = (uint32_t)(offB + (warp_n*32 + ntp*16)*40 + ks*16) * 2;
                ldsm4(bhf, bb + OP_BH + bo);
                ldsm4(blf, bb + OP_BL + bo);
                #pragma unroll
                for (int mt = 0; mt < 4; mt++) {
                    mma_f16(acc[mt][ntp*2],   af[mt], bhf);
                    mma_f16(acc[mt][ntp*2],   af[mt], blf);
                    mma_f16(acc[mt][ntp*2+1], af[mt], bhf + 2);
                    mma_f16(acc[mt][ntp*2+1], af[mt], blf + 2);
                }
            }
        }
    }

    #pragma unroll
    for (int mt = 0; mt < 4; mt++)
        #pragma unroll
        for (int nt = 0; nt < 4; nt++) {
            int n = n0 + warp_n * 32 + nt * 8 + tig * 2;
            int m = m0 + warp_m * 64 + mt * 16 + gid;
            {
                size_t off = (size_t)m * EMB + n;
                float2 xv = *(const float2*)&x[off];
                *(float2*)&out[off] = make_float2(acc[mt][nt][0] + xv.x, acc[mt][nt][1] + xv.y);
            }
            {
                size_t off = (size_t)(m + 8) * EMB + n;
                float2 xv = *(const float2*)&x[off];
                *(float2*)&out[off] = make_float2(acc[mt][nt][2] + xv.x, acc[mt][nt][3] + xv.y);
            }
        }
}

extern "C" void kernel_launch(void* const* d_in, const int* in_sizes, int n_in,
                              void* d_out, int out_size)
{
    const float* x  = (const float*)d_in[0];
    const float* Wq = (const float*)d_in[1];
    const float* Wk = (const float*)d_in[2];
    const float* Wv = (const float*)d_in[3];
    const float* Wo = (const float*)d_in[4];
    float* out = (float*)d_out;

    cudaFuncSetAttribute(qkv_mma_kernel, cudaFuncAttributeMaxDynamicSharedMemorySize, QKV_SMEM);
    cudaFuncSetAttribute(attn_mma_kernel, cudaFuncAttributeMaxDynamicSharedMemorySize, ATTN_SMEM);
    cudaFuncSetAttribute(outproj_mma_kernel, cudaFuncAttributeMaxDynamicSharedMemorySize, OP_SMEM);

    prep_kernel<<<PREP_TOT / 256, 256>>>(x, Wq, Wk, Wv, Wo);

    dim3 g1(NTOK / 128, 3 * EMB / 128);   // (32, 24)
    qkv_mma_kernel<<<g1, 256, QKV_SMEM>>>();

    dim3 g2(TSEQ / 128, NHEAD, NBATCH);
    attn_mma_kernel<<<g2, 256, ATTN_SMEM>>>();

    dim3 g3(NTOK / 128, EMB / 128);
    outproj_mma_kernel<<<g3, 256, OP_SMEM>>>(x, out);
}